// round 1
// baseline (speedup 1.0000x reference)
#include <cuda_runtime.h>

// Problem constants (fixed by the reference)
#define BATCH 2
#define SEQ   2048
#define EMB   1024
#define NH    16
#define HD    64
#define MROWS (BATCH * SEQ)   // 4096

// Scratch (device globals — no allocation allowed)
__device__ float g_Q[BATCH * NH * SEQ * HD];  // [B,H,S,D]
__device__ float g_K[BATCH * NH * SEQ * HD];
__device__ float g_V[BATCH * NH * SEQ * HD];
__device__ float g_O[BATCH * SEQ * EMB];      // [B,S,E] (heads concatenated)

// ---------------------------------------------------------------------------
// GEMM: out = A[4096x1024] @ W[1024x1024] + bias
// BM=BN=128, BK=8, 256 threads, 8x8 micro-tile per thread.
// MODE 0: scatter to head-major [B,H,S,D]; MODE 1: plain [M,N].
// ---------------------------------------------------------------------------
template <int MODE>
__device__ __forceinline__ void gemm_body(const float* __restrict__ A,
                                          const float* __restrict__ W,
                                          const float* __restrict__ bias,
                                          float* __restrict__ out)
{
    __shared__ float As[8][128];   // [k][m]
    __shared__ float Bs[8][128];   // [k][n]

    const int tid = threadIdx.x;
    const int tx  = tid & 15;      // 0..15 -> n
    const int ty  = tid >> 4;      // 0..15 -> m
    const int m0  = blockIdx.y * 128;
    const int n0  = blockIdx.x * 128;

    float acc[8][8];
    #pragma unroll
    for (int i = 0; i < 8; i++)
        #pragma unroll
        for (int j = 0; j < 8; j++) acc[i][j] = 0.0f;

    const int ar  = tid >> 1;          // A tile row 0..127
    const int ac  = (tid & 1) * 4;     // A tile col {0,4}
    const int bkr = tid >> 5;          // B tile row 0..7
    const int bc  = (tid & 31) * 4;    // B tile col

    for (int k0 = 0; k0 < EMB; k0 += 8) {
        float4 va = *(const float4*)&A[(size_t)(m0 + ar) * EMB + k0 + ac];
        As[ac + 0][ar] = va.x;
        As[ac + 1][ar] = va.y;
        As[ac + 2][ar] = va.z;
        As[ac + 3][ar] = va.w;
        *(float4*)&Bs[bkr][bc] =
            *(const float4*)&W[(size_t)(k0 + bkr) * EMB + n0 + bc];
        __syncthreads();

        #pragma unroll
        for (int kk = 0; kk < 8; kk++) {
            float4 a0 = *(float4*)&As[kk][ty * 8];
            float4 a1 = *(float4*)&As[kk][ty * 8 + 4];
            float4 b0 = *(float4*)&Bs[kk][tx * 8];
            float4 b1 = *(float4*)&Bs[kk][tx * 8 + 4];
            float av[8] = {a0.x, a0.y, a0.z, a0.w, a1.x, a1.y, a1.z, a1.w};
            float bv[8] = {b0.x, b0.y, b0.z, b0.w, b1.x, b1.y, b1.z, b1.w};
            #pragma unroll
            for (int i = 0; i < 8; i++)
                #pragma unroll
                for (int j = 0; j < 8; j++)
                    acc[i][j] += av[i] * bv[j];
        }
        __syncthreads();
    }

    #pragma unroll
    for (int i = 0; i < 8; i++) {
        const int row = m0 + ty * 8 + i;
        #pragma unroll
        for (int j = 0; j < 8; j++) {
            const int col = n0 + tx * 8 + j;
            float v = acc[i][j] + bias[col];
            if (MODE == 0) {
                const int b = row >> 11, s = row & 2047;
                const int h = col >> 6,  d = col & 63;
                out[((size_t)((b << 4) + h) * SEQ + s) * HD + d] = v;
            } else {
                out[(size_t)row * EMB + col] = v;
            }
        }
    }
}

__global__ __launch_bounds__(256)
void qkv_gemm_kernel(const float* __restrict__ x,
                     const float* __restrict__ Wq, const float* __restrict__ bq,
                     const float* __restrict__ Wk, const float* __restrict__ bk,
                     const float* __restrict__ Wv, const float* __restrict__ bv)
{
    const float* W; const float* bias; float* out;
    if (blockIdx.z == 0)      { W = Wq; bias = bq; out = g_Q; }
    else if (blockIdx.z == 1) { W = Wk; bias = bk; out = g_K; }
    else                      { W = Wv; bias = bv; out = g_V; }
    gemm_body<0>(x, W, bias, out);
}

__global__ __launch_bounds__(256)
void proj_gemm_kernel(const float* __restrict__ Wo,
                      const float* __restrict__ bo,
                      float* __restrict__ out)
{
    gemm_body<1>(g_O, Wo, bo, out);
}

// ---------------------------------------------------------------------------
// Flash attention (fp32): grid (32 q-blocks, 32 b*h), 256 threads.
// 64-query block, 32-key tiles, online softmax.
// Thread map (tx 0..15, ty 0..15): scores tile 4q x 2k; PV tile 4q x 4d.
// ---------------------------------------------------------------------------
__global__ __launch_bounds__(256)
void attn_kernel()
{
    __shared__ float Qt[HD][68];   // [d][q]  (q-tile 64, scaled by 1/8)
    __shared__ float Kt[HD][34];   // [d][k]  (k-tile 32)
    __shared__ float Vs[32][68];   // [k][d]
    __shared__ float Ps[64][34];   // [q][k]

    const int tid = threadIdx.x;
    const int tx  = tid & 15;
    const int ty  = tid >> 4;
    const int qb  = blockIdx.x;    // 0..31
    const int bh  = blockIdx.y;    // 0..31

    const float* Qbase = g_Q + (size_t)bh * SEQ * HD + (size_t)qb * 64 * HD;
    const float* Kbase = g_K + (size_t)bh * SEQ * HD;
    const float* Vbase = g_V + (size_t)bh * SEQ * HD;

    // Load Q tile transposed + pre-scaled by 1/sqrt(D) = 0.125
    {
        const int q  = tid >> 2;           // 0..63
        const int d0 = (tid & 3) * 16;     // 16 floats per thread
        #pragma unroll
        for (int u = 0; u < 16; u += 4) {
            float4 v = *(const float4*)&Qbase[(size_t)q * HD + d0 + u];
            Qt[d0 + u + 0][q] = v.x * 0.125f;
            Qt[d0 + u + 1][q] = v.y * 0.125f;
            Qt[d0 + u + 2][q] = v.z * 0.125f;
            Qt[d0 + u + 3][q] = v.w * 0.125f;
        }
    }

    float m_i[4], l_i[4], acc[4][4];
    #pragma unroll
    for (int i = 0; i < 4; i++) {
        m_i[i] = -1e30f;
        l_i[i] = 0.0f;
        #pragma unroll
        for (int j = 0; j < 4; j++) acc[i][j] = 0.0f;
    }

    const int lk = tid >> 3;            // 0..31 : K/V tile row
    const int ld = (tid & 7) * 8;       // 8 floats per thread

    for (int kt = 0; kt < SEQ; kt += 32) {
        __syncthreads();   // protect Kt/Vs/Ps from previous iteration readers
        // K tile transposed
        #pragma unroll
        for (int u = 0; u < 8; u += 4) {
            float4 v = *(const float4*)&Kbase[(size_t)(kt + lk) * HD + ld + u];
            Kt[ld + u + 0][lk] = v.x;
            Kt[ld + u + 1][lk] = v.y;
            Kt[ld + u + 2][lk] = v.z;
            Kt[ld + u + 3][lk] = v.w;
        }
        // V tile natural
        #pragma unroll
        for (int u = 0; u < 8; u += 4) {
            *(float4*)&Vs[lk][ld + u] =
                *(const float4*)&Vbase[(size_t)(kt + lk) * HD + ld + u];
        }
        __syncthreads();

        // Scores: s[q = ty*4+i][k = tx*2+{0,1}]
        float sA[4] = {0.f, 0.f, 0.f, 0.f};
        float sB[4] = {0.f, 0.f, 0.f, 0.f};
        #pragma unroll 16
        for (int d = 0; d < HD; d++) {
            float4 a = *(float4*)&Qt[d][ty * 4];
            float2 b = *(float2*)&Kt[d][tx * 2];
            sA[0] += a.x * b.x; sA[1] += a.y * b.x;
            sA[2] += a.z * b.x; sA[3] += a.w * b.x;
            sB[0] += a.x * b.y; sB[1] += a.y * b.y;
            sB[2] += a.z * b.y; sB[3] += a.w * b.y;
        }

        // Online softmax (row reduction across the 16 tx lanes of each half-warp)
        #pragma unroll
        for (int i = 0; i < 4; i++) {
            float rm = fmaxf(sA[i], sB[i]);
            #pragma unroll
            for (int o = 8; o > 0; o >>= 1)
                rm = fmaxf(rm, __shfl_xor_sync(0xffffffffu, rm, o));
            const float mn   = fmaxf(m_i[i], rm);
            const float corr = __expf(m_i[i] - mn);
            m_i[i] = mn;
            const float p0 = __expf(sA[i] - mn);
            const float p1 = __expf(sB[i] - mn);
            float rs = p0 + p1;
            #pragma unroll
            for (int o = 8; o > 0; o >>= 1)
                rs += __shfl_xor_sync(0xffffffffu, rs, o);
            l_i[i] = l_i[i] * corr + rs;
            acc[i][0] *= corr; acc[i][1] *= corr;
            acc[i][2] *= corr; acc[i][3] *= corr;
            Ps[ty * 4 + i][tx * 2 + 0] = p0;
            Ps[ty * 4 + i][tx * 2 + 1] = p1;
        }
        __syncthreads();

        // O += P @ V : O[q = ty*4+i][d = tx*4+j]
        #pragma unroll 8
        for (int k = 0; k < 32; k++) {
            float4 v4 = *(float4*)&Vs[k][tx * 4];
            float p0 = Ps[ty * 4 + 0][k];
            float p1 = Ps[ty * 4 + 1][k];
            float p2 = Ps[ty * 4 + 2][k];
            float p3 = Ps[ty * 4 + 3][k];
            acc[0][0] += p0 * v4.x; acc[0][1] += p0 * v4.y;
            acc[0][2] += p0 * v4.z; acc[0][3] += p0 * v4.w;
            acc[1][0] += p1 * v4.x; acc[1][1] += p1 * v4.y;
            acc[1][2] += p1 * v4.z; acc[1][3] += p1 * v4.w;
            acc[2][0] += p2 * v4.x; acc[2][1] += p2 * v4.y;
            acc[2][2] += p2 * v4.z; acc[2][3] += p2 * v4.w;
            acc[3][0] += p3 * v4.x; acc[3][1] += p3 * v4.y;
            acc[3][2] += p3 * v4.z; acc[3][3] += p3 * v4.w;
        }
    }

    // Epilogue: normalize and write [B,S,E] (heads concatenated on E)
    const int b = bh >> 4, h = bh & 15;
    #pragma unroll
    for (int i = 0; i < 4; i++) {
        const float inv = 1.0f / l_i[i];
        const int sg = qb * 64 + ty * 4 + i;
        float4 o;
        o.x = acc[i][0] * inv; o.y = acc[i][1] * inv;
        o.z = acc[i][2] * inv; o.w = acc[i][3] * inv;
        *(float4*)&g_O[((size_t)(b * SEQ + sg)) * EMB + h * HD + tx * 4] = o;
    }
}

// ---------------------------------------------------------------------------
extern "C" void kernel_launch(void* const* d_in, const int* in_sizes, int n_in,
                              void* d_out, int out_size)
{
    const float* x  = (const float*)d_in[0];
    const float* Wq = (const float*)d_in[1];
    const float* bq = (const float*)d_in[2];
    const float* Wk = (const float*)d_in[3];
    const float* bk = (const float*)d_in[4];
    const float* Wv = (const float*)d_in[5];
    const float* bv = (const float*)d_in[6];
    const float* Wo = (const float*)d_in[7];
    const float* bo = (const float*)d_in[8];
    float* out = (float*)d_out;

    // 1) QKV projections -> head-major scratch
    qkv_gemm_kernel<<<dim3(EMB / 128, MROWS / 128, 3), 256>>>(
        x, Wq, bq, Wk, bk, Wv, bv);

    // 2) Flash attention -> g_O [B,S,E]
    attn_kernel<<<dim3(SEQ / 64, BATCH * NH), 256>>>();

    // 3) Output projection -> d_out
    proj_gemm_kernel<<<dim3(EMB / 128, MROWS / 128), 256>>>(Wo, bo, out);
}

// round 4
// speedup vs baseline: 1.3523x; 1.3523x over previous
#include <cuda_runtime.h>
#include <cstdint>

// Problem constants (fixed by the reference)
#define BATCH 2
#define SEQ   2048
#define EMB   1024
#define NH    16
#define HD    64
#define MROWS (BATCH * SEQ)   // 4096

// Scratch (device globals — no allocation allowed)
__device__ float g_Q[BATCH * NH * SEQ * HD];  // [B,H,S,D]
__device__ float g_K[BATCH * NH * SEQ * HD];
__device__ float g_V[BATCH * NH * SEQ * HD];
__device__ float g_O[BATCH * SEQ * EMB];      // [B,S,E] (heads concatenated)

// ---------------------------------------------------------------------------
// mma.sync tf32 helpers (plain sm_103 — no 'a'-feature instructions)
// ---------------------------------------------------------------------------
__device__ __forceinline__ uint32_t cvt_tf32(float f) {
    uint32_t r;
    asm("cvt.rna.tf32.f32 %0, %1;" : "=r"(r) : "f"(f));
    return r;
}

// D(16x8,f32) += A(16x8,tf32) * B(8x8,tf32)
__device__ __forceinline__ void mma_tf32(float* d, const uint32_t* a,
                                         const uint32_t* b) {
    asm volatile(
        "mma.sync.aligned.m16n8k8.row.col.f32.tf32.tf32.f32 "
        "{%0,%1,%2,%3}, {%4,%5,%6,%7}, {%8,%9}, {%0,%1,%2,%3};"
        : "+f"(d[0]), "+f"(d[1]), "+f"(d[2]), "+f"(d[3])
        : "r"(a[0]), "r"(a[1]), "r"(a[2]), "r"(a[3]),
          "r"(b[0]), "r"(b[1]));
}

// ---------------------------------------------------------------------------
// tf32 warp-MMA GEMM: out = A[4096x1024] @ W[1024x1024] + bias
// BM=BN=128, BK=32, 256 threads = 8 warps (4m x 2n), warp tile 32m x 64n.
// Smem strides chosen for conflict-free fragment LDS:
//   As[m][k] stride 36 -> bank = (4*(lane>>2) + k) distinct per lane
//   Bs[k][n] stride 136 -> bank = (8*(lane&3) + (lane>>2)) distinct per lane
// MODE 0: scatter to head-major [B,H,S,D]; MODE 1: plain [M,N].
// ---------------------------------------------------------------------------
template <int MODE>
__device__ __forceinline__ void mma_gemm_body(const float* __restrict__ A,
                                              const float* __restrict__ W,
                                              const float* __restrict__ bias,
                                              float* __restrict__ out)
{
    __shared__ __align__(16) uint32_t As[128][36];   // 18432 B
    __shared__ __align__(16) uint32_t Bs[32][136];   // 17408 B

    const int tid  = threadIdx.x;
    const int lane = tid & 31;
    const int wid  = tid >> 5;
    const int wm   = wid >> 1;       // 0..3 -> m offset 32 each
    const int wn   = wid & 1;        // 0..1 -> n offset 64 each
    const int m0   = blockIdx.y * 128;
    const int n0   = blockIdx.x * 128;

    // Global load maps
    const int am = tid >> 1;               // A tile row 0..127
    const int ak = (tid & 1) * 16;         // A tile col base {0,16}
    const float* Aptr = A + (size_t)(m0 + am) * EMB + ak;
    const int bk = tid >> 3;               // W tile row (k) 0..31
    const int bn = (tid & 7) * 16;         // W tile col base
    const float* Wptr = W + (size_t)bk * EMB + n0 + bn;

    float4 ra[4], rb[4];
    #pragma unroll
    for (int u = 0; u < 4; u++) ra[u] = *(const float4*)(Aptr + u * 4);
    #pragma unroll
    for (int u = 0; u < 4; u++) rb[u] = *(const float4*)(Wptr + u * 4);

    float acc[2][8][4];
    #pragma unroll
    for (int mf = 0; mf < 2; mf++)
        #pragma unroll
        for (int nf = 0; nf < 8; nf++)
            #pragma unroll
            for (int j = 0; j < 4; j++) acc[mf][nf][j] = 0.0f;

    const int r = lane >> 2;   // 0..7
    const int c = lane & 3;    // 0..3

    for (int it = 0; it < 32; ++it) {
        if (it) __syncthreads();   // previous tile's readers are done

        #pragma unroll
        for (int u = 0; u < 4; u++) {
            uint4 p;
            p.x = cvt_tf32(ra[u].x); p.y = cvt_tf32(ra[u].y);
            p.z = cvt_tf32(ra[u].z); p.w = cvt_tf32(ra[u].w);
            *(uint4*)&As[am][ak + u * 4] = p;
            uint4 q;
            q.x = cvt_tf32(rb[u].x); q.y = cvt_tf32(rb[u].y);
            q.z = cvt_tf32(rb[u].z); q.w = cvt_tf32(rb[u].w);
            *(uint4*)&Bs[bk][bn + u * 4] = q;
        }
        __syncthreads();

        // Prefetch next tile while this one computes
        if (it + 1 < 32) {
            const float* Ap = Aptr + (it + 1) * 32;
            const float* Wp = Wptr + (size_t)(it + 1) * 32 * EMB;
            #pragma unroll
            for (int u = 0; u < 4; u++) ra[u] = *(const float4*)(Ap + u * 4);
            #pragma unroll
            for (int u = 0; u < 4; u++) rb[u] = *(const float4*)(Wp + u * 4);
        }

        #pragma unroll
        for (int ks = 0; ks < 4; ks++) {
            const int kk = ks * 8;
            uint32_t af[2][4];
            #pragma unroll
            for (int mf = 0; mf < 2; mf++) {
                const int m = wm * 32 + mf * 16 + r;
                af[mf][0] = As[m][kk + c];
                af[mf][1] = As[m + 8][kk + c];
                af[mf][2] = As[m][kk + c + 4];
                af[mf][3] = As[m + 8][kk + c + 4];
            }
            #pragma unroll
            for (int nf = 0; nf < 8; nf++) {
                const int n = wn * 64 + nf * 8 + r;
                uint32_t bf[2];
                bf[0] = Bs[kk + c][n];
                bf[1] = Bs[kk + c + 4][n];
                mma_tf32(acc[0][nf], af[0], bf);
                mma_tf32(acc[1][nf], af[1], bf);
            }
        }
    }

    // Epilogue: bias add + store.
    // D frag: row = r (+8), col = 2*(lane&3) (+1) within each 16x8 tile.
    const int c2 = (lane & 3) * 2;
    #pragma unroll
    for (int mf = 0; mf < 2; mf++) {
        const int row0 = m0 + wm * 32 + mf * 16 + r;
        #pragma unroll
        for (int nf = 0; nf < 8; nf++) {
            const int col = n0 + wn * 64 + nf * 8 + c2;
            const float b0 = bias[col], b1 = bias[col + 1];
            float2 v0, v1;
            v0.x = acc[mf][nf][0] + b0; v0.y = acc[mf][nf][1] + b1;
            v1.x = acc[mf][nf][2] + b0; v1.y = acc[mf][nf][3] + b1;
            if (MODE == 0) {
                const int h = col >> 6, d = col & 63;
                {
                    const int b = row0 >> 11, s = row0 & 2047;
                    *(float2*)&out[((size_t)((b << 4) + h) * SEQ + s) * HD + d] = v0;
                }
                {
                    const int row1 = row0 + 8;
                    const int b = row1 >> 11, s = row1 & 2047;
                    *(float2*)&out[((size_t)((b << 4) + h) * SEQ + s) * HD + d] = v1;
                }
            } else {
                *(float2*)&out[(size_t)row0 * EMB + col] = v0;
                *(float2*)&out[(size_t)(row0 + 8) * EMB + col] = v1;
            }
        }
    }
}

__global__ __launch_bounds__(256, 2)
void qkv_gemm_kernel(const float* __restrict__ x,
                     const float* __restrict__ Wq, const float* __restrict__ bq,
                     const float* __restrict__ Wk, const float* __restrict__ bk,
                     const float* __restrict__ Wv, const float* __restrict__ bv)
{
    const float* W; const float* bias; float* out;
    if (blockIdx.z == 0)      { W = Wq; bias = bq; out = g_Q; }
    else if (blockIdx.z == 1) { W = Wk; bias = bk; out = g_K; }
    else                      { W = Wv; bias = bv; out = g_V; }
    mma_gemm_body<0>(x, W, bias, out);
}

__global__ __launch_bounds__(256, 2)
void proj_gemm_kernel(const float* __restrict__ Wo,
                      const float* __restrict__ bo,
                      float* __restrict__ out)
{
    mma_gemm_body<1>(g_O, Wo, bo, out);
}

// ---------------------------------------------------------------------------
// Flash attention (fp32): grid (32 q-blocks, 32 b*h), 256 threads.
// 64-query block, 32-key tiles, online softmax. (unchanged, validated in R0)
// ---------------------------------------------------------------------------
__global__ __launch_bounds__(256)
void attn_kernel()
{
    __shared__ float Qt[HD][68];   // [d][q]  (q-tile 64, scaled by 1/8)
    __shared__ float Kt[HD][34];   // [d][k]  (k-tile 32)
    __shared__ float Vs[32][68];   // [k][d]
    __shared__ float Ps[64][34];   // [q][k]

    const int tid = threadIdx.x;
    const int tx  = tid & 15;
    const int ty  = tid >> 4;
    const int qb  = blockIdx.x;    // 0..31
    const int bh  = blockIdx.y;    // 0..31

    const float* Qbase = g_Q + (size_t)bh * SEQ * HD + (size_t)qb * 64 * HD;
    const float* Kbase = g_K + (size_t)bh * SEQ * HD;
    const float* Vbase = g_V + (size_t)bh * SEQ * HD;

    // Load Q tile transposed + pre-scaled by 1/sqrt(D) = 0.125
    {
        const int q  = tid >> 2;           // 0..63
        const int d0 = (tid & 3) * 16;     // 16 floats per thread
        #pragma unroll
        for (int u = 0; u < 16; u += 4) {
            float4 v = *(const float4*)&Qbase[(size_t)q * HD + d0 + u];
            Qt[d0 + u + 0][q] = v.x * 0.125f;
            Qt[d0 + u + 1][q] = v.y * 0.125f;
            Qt[d0 + u + 2][q] = v.z * 0.125f;
            Qt[d0 + u + 3][q] = v.w * 0.125f;
        }
    }

    float m_i[4], l_i[4], acc[4][4];
    #pragma unroll
    for (int i = 0; i < 4; i++) {
        m_i[i] = -1e30f;
        l_i[i] = 0.0f;
        #pragma unroll
        for (int j = 0; j < 4; j++) acc[i][j] = 0.0f;
    }

    const int lk = tid >> 3;            // 0..31 : K/V tile row
    const int ld = (tid & 7) * 8;       // 8 floats per thread

    for (int kt = 0; kt < SEQ; kt += 32) {
        __syncthreads();   // protect Kt/Vs/Ps from previous iteration readers
        // K tile transposed
        #pragma unroll
        for (int u = 0; u < 8; u += 4) {
            float4 v = *(const float4*)&Kbase[(size_t)(kt + lk) * HD + ld + u];
            Kt[ld + u + 0][lk] = v.x;
            Kt[ld + u + 1][lk] = v.y;
            Kt[ld + u + 2][lk] = v.z;
            Kt[ld + u + 3][lk] = v.w;
        }
        // V tile natural
        #pragma unroll
        for (int u = 0; u < 8; u += 4) {
            *(float4*)&Vs[lk][ld + u] =
                *(const float4*)&Vbase[(size_t)(kt + lk) * HD + ld + u];
        }
        __syncthreads();

        // Scores: s[q = ty*4+i][k = tx*2+{0,1}]
        float sA[4] = {0.f, 0.f, 0.f, 0.f};
        float sB[4] = {0.f, 0.f, 0.f, 0.f};
        #pragma unroll 16
        for (int d = 0; d < HD; d++) {
            float4 a = *(float4*)&Qt[d][ty * 4];
            float2 b = *(float2*)&Kt[d][tx * 2];
            sA[0] += a.x * b.x; sA[1] += a.y * b.x;
            sA[2] += a.z * b.x; sA[3] += a.w * b.x;
            sB[0] += a.x * b.y; sB[1] += a.y * b.y;
            sB[2] += a.z * b.y; sB[3] += a.w * b.y;
        }

        // Online softmax (row reduction across the 16 tx lanes of each half-warp)
        #pragma unroll
        for (int i = 0; i < 4; i++) {
            float rm = fmaxf(sA[i], sB[i]);
            #pragma unroll
            for (int o = 8; o > 0; o >>= 1)
                rm = fmaxf(rm, __shfl_xor_sync(0xffffffffu, rm, o));
            const float mn   = fmaxf(m_i[i], rm);
            const float corr = __expf(m_i[i] - mn);
            m_i[i] = mn;
            const float p0 = __expf(sA[i] - mn);
            const float p1 = __expf(sB[i] - mn);
            float rs = p0 + p1;
            #pragma unroll
            for (int o = 8; o > 0; o >>= 1)
                rs += __shfl_xor_sync(0xffffffffu, rs, o);
            l_i[i] = l_i[i] * corr + rs;
            acc[i][0] *= corr; acc[i][1] *= corr;
            acc[i][2] *= corr; acc[i][3] *= corr;
            Ps[ty * 4 + i][tx * 2 + 0] = p0;
            Ps[ty * 4 + i][tx * 2 + 1] = p1;
        }
        __syncthreads();

        // O += P @ V : O[q = ty*4+i][d = tx*4+j]
        #pragma unroll 8
        for (int k = 0; k < 32; k++) {
            float4 v4 = *(float4*)&Vs[k][tx * 4];
            float p0 = Ps[ty * 4 + 0][k];
            float p1 = Ps[ty * 4 + 1][k];
            float p2 = Ps[ty * 4 + 2][k];
            float p3 = Ps[ty * 4 + 3][k];
            acc[0][0] += p0 * v4.x; acc[0][1] += p0 * v4.y;
            acc[0][2] += p0 * v4.z; acc[0][3] += p0 * v4.w;
            acc[1][0] += p1 * v4.x; acc[1][1] += p1 * v4.y;
            acc[1][2] += p1 * v4.z; acc[1][3] += p1 * v4.w;
            acc[2][0] += p2 * v4.x; acc[2][1] += p2 * v4.y;
            acc[2][2] += p2 * v4.z; acc[2][3] += p2 * v4.w;
            acc[3][0] += p3 * v4.x; acc[3][1] += p3 * v4.y;
            acc[3][2] += p3 * v4.z; acc[3][3] += p3 * v4.w;
        }
    }

    // Epilogue: normalize and write [B,S,E] (heads concatenated on E)
    const int b = bh >> 4, h = bh & 15;
    #pragma unroll
    for (int i = 0; i < 4; i++) {
        const float inv = 1.0f / l_i[i];
        const int sg = qb * 64 + ty * 4 + i;
        float4 o;
        o.x = acc[i][0] * inv; o.y = acc[i][1] * inv;
        o.z = acc[i][2] * inv; o.w = acc[i][3] * inv;
        *(float4*)&g_O[((size_t)(b * SEQ + sg)) * EMB + h * HD + tx * 4] = o;
    }
}

// ---------------------------------------------------------------------------
extern "C" void kernel_launch(void* const* d_in, const int* in_sizes, int n_in,
                              void* d_out, int out_size)
{
    const float* x  = (const float*)d_in[0];
    const float* Wq = (const float*)d_in[1];
    const float* bq = (const float*)d_in[2];
    const float* Wk = (const float*)d_in[3];
    const float* bk = (const float*)d_in[4];
    const float* Wv = (const float*)d_in[5];
    const float* bv = (const float*)d_in[6];
    const float* Wo = (const float*)d_in[7];
    const float* bo = (const float*)d_in[8];
    float* out = (float*)d_out;

    // 1) QKV projections (tf32 mma.sync) -> head-major scratch
    qkv_gemm_kernel<<<dim3(EMB / 128, MROWS / 128, 3), 256>>>(
        x, Wq, bq, Wk, bk, Wv, bv);

    // 2) Flash attention (fp32 SIMT) -> g_O [B,S,E]
    attn_kernel<<<dim3(SEQ / 64, BATCH * NH), 256>>>();

    // 3) Output projection (tf32 mma.sync) -> d_out
    proj_gemm_kernel<<<dim3(EMB / 128, MROWS / 128), 256>>>(Wo, bo, out);
}

// round 5
// speedup vs baseline: 2.7673x; 2.0463x over previous
#include <cuda_runtime.h>
#include <cstdint>

// Problem constants (fixed by the reference)
#define BATCH 2
#define SEQ   2048
#define EMB   1024
#define NH    16
#define HD    64
#define MROWS (BATCH * SEQ)   // 4096

// Scratch (device globals — no allocation allowed)
__device__ float g_Q[BATCH * NH * SEQ * HD];  // [B,H,S,D]
__device__ float g_K[BATCH * NH * SEQ * HD];
__device__ float g_V[BATCH * NH * SEQ * HD];
__device__ float g_O[BATCH * SEQ * EMB];      // [B,S,E] (heads concatenated)

// ---------------------------------------------------------------------------
// mma.sync tf32 helpers (plain sm_103 — no 'a'-feature instructions)
// ---------------------------------------------------------------------------
__device__ __forceinline__ uint32_t cvt_tf32(float f) {
    uint32_t r;
    asm("cvt.rna.tf32.f32 %0, %1;" : "=r"(r) : "f"(f));
    return r;
}

// D(16x8,f32) += A(16x8,tf32) * B(8x8,tf32)
__device__ __forceinline__ void mma_tf32(float* d, const uint32_t* a,
                                         const uint32_t* b) {
    asm volatile(
        "mma.sync.aligned.m16n8k8.row.col.f32.tf32.tf32.f32 "
        "{%0,%1,%2,%3}, {%4,%5,%6,%7}, {%8,%9}, {%0,%1,%2,%3};"
        : "+f"(d[0]), "+f"(d[1]), "+f"(d[2]), "+f"(d[3])
        : "r"(a[0]), "r"(a[1]), "r"(a[2]), "r"(a[3]),
          "r"(b[0]), "r"(b[1]));
}

// ---------------------------------------------------------------------------
// tf32 warp-MMA GEMM: out = A[4096x1024] @ W[1024x1024] + bias  (unchanged R4)
// ---------------------------------------------------------------------------
template <int MODE>
__device__ __forceinline__ void mma_gemm_body(const float* __restrict__ A,
                                              const float* __restrict__ W,
                                              const float* __restrict__ bias,
                                              float* __restrict__ out)
{
    __shared__ __align__(16) uint32_t As[128][36];   // 18432 B
    __shared__ __align__(16) uint32_t Bs[32][136];   // 17408 B

    const int tid  = threadIdx.x;
    const int lane = tid & 31;
    const int wid  = tid >> 5;
    const int wm   = wid >> 1;
    const int wn   = wid & 1;
    const int m0   = blockIdx.y * 128;
    const int n0   = blockIdx.x * 128;

    const int am = tid >> 1;
    const int ak = (tid & 1) * 16;
    const float* Aptr = A + (size_t)(m0 + am) * EMB + ak;
    const int bk = tid >> 3;
    const int bn = (tid & 7) * 16;
    const float* Wptr = W + (size_t)bk * EMB + n0 + bn;

    float4 ra[4], rb[4];
    #pragma unroll
    for (int u = 0; u < 4; u++) ra[u] = *(const float4*)(Aptr + u * 4);
    #pragma unroll
    for (int u = 0; u < 4; u++) rb[u] = *(const float4*)(Wptr + u * 4);

    float acc[2][8][4];
    #pragma unroll
    for (int mf = 0; mf < 2; mf++)
        #pragma unroll
        for (int nf = 0; nf < 8; nf++)
            #pragma unroll
            for (int j = 0; j < 4; j++) acc[mf][nf][j] = 0.0f;

    const int r = lane >> 2;
    const int c = lane & 3;

    for (int it = 0; it < 32; ++it) {
        if (it) __syncthreads();

        #pragma unroll
        for (int u = 0; u < 4; u++) {
            uint4 p;
            p.x = cvt_tf32(ra[u].x); p.y = cvt_tf32(ra[u].y);
            p.z = cvt_tf32(ra[u].z); p.w = cvt_tf32(ra[u].w);
            *(uint4*)&As[am][ak + u * 4] = p;
            uint4 q;
            q.x = cvt_tf32(rb[u].x); q.y = cvt_tf32(rb[u].y);
            q.z = cvt_tf32(rb[u].z); q.w = cvt_tf32(rb[u].w);
            *(uint4*)&Bs[bk][bn + u * 4] = q;
        }
        __syncthreads();

        if (it + 1 < 32) {
            const float* Ap = Aptr + (it + 1) * 32;
            const float* Wp = Wptr + (size_t)(it + 1) * 32 * EMB;
            #pragma unroll
            for (int u = 0; u < 4; u++) ra[u] = *(const float4*)(Ap + u * 4);
            #pragma unroll
            for (int u = 0; u < 4; u++) rb[u] = *(const float4*)(Wp + u * 4);
        }

        #pragma unroll
        for (int ks = 0; ks < 4; ks++) {
            const int kk = ks * 8;
            uint32_t af[2][4];
            #pragma unroll
            for (int mf = 0; mf < 2; mf++) {
                const int m = wm * 32 + mf * 16 + r;
                af[mf][0] = As[m][kk + c];
                af[mf][1] = As[m + 8][kk + c];
                af[mf][2] = As[m][kk + c + 4];
                af[mf][3] = As[m + 8][kk + c + 4];
            }
            #pragma unroll
            for (int nf = 0; nf < 8; nf++) {
                const int n = wn * 64 + nf * 8 + r;
                uint32_t bf[2];
                bf[0] = Bs[kk + c][n];
                bf[1] = Bs[kk + c + 4][n];
                mma_tf32(acc[0][nf], af[0], bf);
                mma_tf32(acc[1][nf], af[1], bf);
            }
        }
    }

    const int c2 = (lane & 3) * 2;
    #pragma unroll
    for (int mf = 0; mf < 2; mf++) {
        const int row0 = m0 + wm * 32 + mf * 16 + r;
        #pragma unroll
        for (int nf = 0; nf < 8; nf++) {
            const int col = n0 + wn * 64 + nf * 8 + c2;
            const float b0 = bias[col], b1 = bias[col + 1];
            float2 v0, v1;
            v0.x = acc[mf][nf][0] + b0; v0.y = acc[mf][nf][1] + b1;
            v1.x = acc[mf][nf][2] + b0; v1.y = acc[mf][nf][3] + b1;
            if (MODE == 0) {
                const int h = col >> 6, d = col & 63;
                {
                    const int b = row0 >> 11, s = row0 & 2047;
                    *(float2*)&out[((size_t)((b << 4) + h) * SEQ + s) * HD + d] = v0;
                }
                {
                    const int row1 = row0 + 8;
                    const int b = row1 >> 11, s = row1 & 2047;
                    *(float2*)&out[((size_t)((b << 4) + h) * SEQ + s) * HD + d] = v1;
                }
            } else {
                *(float2*)&out[(size_t)row0 * EMB + col] = v0;
                *(float2*)&out[(size_t)(row0 + 8) * EMB + col] = v1;
            }
        }
    }
}

__global__ __launch_bounds__(256, 2)
void qkv_gemm_kernel(const float* __restrict__ x,
                     const float* __restrict__ Wq, const float* __restrict__ bq,
                     const float* __restrict__ Wk, const float* __restrict__ bk,
                     const float* __restrict__ Wv, const float* __restrict__ bv)
{
    const float* W; const float* bias; float* out;
    if (blockIdx.z == 0)      { W = Wq; bias = bq; out = g_Q; }
    else if (blockIdx.z == 1) { W = Wk; bias = bk; out = g_K; }
    else                      { W = Wv; bias = bv; out = g_V; }
    mma_gemm_body<0>(x, W, bias, out);
}

__global__ __launch_bounds__(256, 2)
void proj_gemm_kernel(const float* __restrict__ Wo,
                      const float* __restrict__ bo,
                      float* __restrict__ out)
{
    mma_gemm_body<1>(g_O, Wo, bo, out);
}

// ---------------------------------------------------------------------------
// Tensor-core flash attention (tf32 mma.sync).
// Grid (32 q-blocks, 32 b*h), 128 threads = 4 warps.
// CTA: 64 queries; warp w owns queries [w*16, w*16+16), all 64 keys per tile.
// Computes S^T = K@Q^T (m=key, n=q, k=d) and O^T = V^T@P^T (m=d, n=q, k=key):
// both K and V are consumed in natural row-major layout (no transposed STS).
// Smem (words): Ks[key][72] at 0 (4608 w), Ps per-warp [key][24] aliased over
// [0,6144), Vs[key][72] at 6144. Total 10752 words = 43008 B.
// Strides 72 and 24 give conflict-free fragment LDS (bank = 8c+r / 24c+r).
// ---------------------------------------------------------------------------
__global__ __launch_bounds__(128, 4)
void attn_kernel()
{
    __shared__ __align__(16) uint32_t SM[10752];
    uint32_t* const Ks = SM;            // [key*72 + d], tf32
    uint32_t* const Vs = SM + 6144;     // [key*72 + d], tf32

    const int tid  = threadIdx.x;
    const int lane = tid & 31;
    const int w    = tid >> 5;
    const int r    = lane >> 2;   // 0..7
    const int c    = lane & 3;    // 0..3
    const int qb   = blockIdx.x;  // 0..31
    const int bh   = blockIdx.y;  // 0..31

    uint32_t* const Psw = SM + w * 1536;   // warp-private P^T [key*24 + q]

    const float* Qbase = g_Q + (size_t)bh * SEQ * HD + (size_t)qb * 64 * HD;
    const float* Kbase = g_K + (size_t)bh * SEQ * HD;
    const float* Vbase = g_V + (size_t)bh * SEQ * HD;

    // Tile-load map: 8 passes, pass covers rows p*8 + (tid>>4), cols (tid&15)*4
    const int lrow = tid >> 4;           // 0..7
    const int lcol = (tid & 15) * 4;     // 0..60

    // ---- Stage Q (raw fp32) into Vs, extract B-fragments (scaled, tf32) ----
    #pragma unroll
    for (int p = 0; p < 8; p++) {
        const int row = p * 8 + lrow;
        *(float4*)&Vs[row * 72 + lcol] =
            *(const float4*)&Qbase[(size_t)row * HD + lcol];
    }
    __syncthreads();

    uint32_t qf[8][2][2];   // [k-oct][nf][b0/b1]
    #pragma unroll
    for (int ks = 0; ks < 8; ks++)
        #pragma unroll
        for (int nf = 0; nf < 2; nf++) {
            const int q = w * 16 + nf * 8 + r;
            qf[ks][nf][0] =
                cvt_tf32(__uint_as_float(Vs[q * 72 + ks * 8 + c]) * 0.125f);
            qf[ks][nf][1] =
                cvt_tf32(__uint_as_float(Vs[q * 72 + ks * 8 + c + 4]) * 0.125f);
        }
    __syncthreads();

    float oacc[4][2][4];    // O^T frags: [d-oct(16)][q-nf][4]
    #pragma unroll
    for (int mf = 0; mf < 4; mf++)
        #pragma unroll
        for (int nf = 0; nf < 2; nf++)
            #pragma unroll
            for (int j = 0; j < 4; j++) oacc[mf][nf][j] = 0.0f;

    float m_s[2][2], l_s[2][2];
    #pragma unroll
    for (int nf = 0; nf < 2; nf++)
        #pragma unroll
        for (int h = 0; h < 2; h++) { m_s[nf][h] = -1e30f; l_s[nf][h] = 0.0f; }

    for (int kt = 0; kt < SEQ; kt += 64) {
        // ---- Load K, V tiles (tf32, natural row layout) ----
        #pragma unroll
        for (int p = 0; p < 8; p++) {
            const int row = p * 8 + lrow;
            float4 kv = *(const float4*)&Kbase[(size_t)(kt + row) * HD + lcol];
            uint4 kp;
            kp.x = cvt_tf32(kv.x); kp.y = cvt_tf32(kv.y);
            kp.z = cvt_tf32(kv.z); kp.w = cvt_tf32(kv.w);
            *(uint4*)&Ks[row * 72 + lcol] = kp;
            float4 vv = *(const float4*)&Vbase[(size_t)(kt + row) * HD + lcol];
            uint4 vp;
            vp.x = cvt_tf32(vv.x); vp.y = cvt_tf32(vv.y);
            vp.z = cvt_tf32(vv.z); vp.w = cvt_tf32(vv.w);
            *(uint4*)&Vs[row * 72 + lcol] = vp;
        }
        __syncthreads();

        // ---- S^T = K @ Q^T : frags [key 64][q 16] ----
        float sacc[4][2][4];
        #pragma unroll
        for (int mf = 0; mf < 4; mf++)
            #pragma unroll
            for (int nf = 0; nf < 2; nf++)
                #pragma unroll
                for (int j = 0; j < 4; j++) sacc[mf][nf][j] = 0.0f;

        #pragma unroll
        for (int ks = 0; ks < 8; ks++) {
            uint32_t af[4][4];
            #pragma unroll
            for (int mf = 0; mf < 4; mf++) {
                const int m = mf * 16 + r;
                af[mf][0] = Ks[m * 72 + ks * 8 + c];
                af[mf][1] = Ks[(m + 8) * 72 + ks * 8 + c];
                af[mf][2] = Ks[m * 72 + ks * 8 + c + 4];
                af[mf][3] = Ks[(m + 8) * 72 + ks * 8 + c + 4];
            }
            #pragma unroll
            for (int mf = 0; mf < 4; mf++) {
                mma_tf32(sacc[mf][0], af[mf], qf[ks][0]);
                mma_tf32(sacc[mf][1], af[mf], qf[ks][1]);
            }
        }

        // ---- Online softmax (key-dim reduction: in-thread + shfl over r) ----
        float corr[2][2];
        #pragma unroll
        for (int nf = 0; nf < 2; nf++)
            #pragma unroll
            for (int h = 0; h < 2; h++) {
                float mx = -1e30f;
                #pragma unroll
                for (int mf = 0; mf < 4; mf++)
                    mx = fmaxf(mx, fmaxf(sacc[mf][nf][h], sacc[mf][nf][h + 2]));
                mx = fmaxf(mx, __shfl_xor_sync(0xffffffffu, mx, 4));
                mx = fmaxf(mx, __shfl_xor_sync(0xffffffffu, mx, 8));
                mx = fmaxf(mx, __shfl_xor_sync(0xffffffffu, mx, 16));
                const float mn = fmaxf(m_s[nf][h], mx);
                corr[nf][h] = __expf(m_s[nf][h] - mn);
                m_s[nf][h] = mn;
            }
        #pragma unroll
        for (int mf = 0; mf < 4; mf++)
            #pragma unroll
            for (int nf = 0; nf < 2; nf++) {
                sacc[mf][nf][0] = __expf(sacc[mf][nf][0] - m_s[nf][0]);
                sacc[mf][nf][1] = __expf(sacc[mf][nf][1] - m_s[nf][1]);
                sacc[mf][nf][2] = __expf(sacc[mf][nf][2] - m_s[nf][0]);
                sacc[mf][nf][3] = __expf(sacc[mf][nf][3] - m_s[nf][1]);
            }
        #pragma unroll
        for (int nf = 0; nf < 2; nf++)
            #pragma unroll
            for (int h = 0; h < 2; h++) {
                float sm = 0.0f;
                #pragma unroll
                for (int mf = 0; mf < 4; mf++)
                    sm += sacc[mf][nf][h] + sacc[mf][nf][h + 2];
                sm += __shfl_xor_sync(0xffffffffu, sm, 4);
                sm += __shfl_xor_sync(0xffffffffu, sm, 8);
                sm += __shfl_xor_sync(0xffffffffu, sm, 16);
                l_s[nf][h] = l_s[nf][h] * corr[nf][h] + sm;
            }
        #pragma unroll
        for (int mf = 0; mf < 4; mf++)
            #pragma unroll
            for (int nf = 0; nf < 2; nf++) {
                oacc[mf][nf][0] *= corr[nf][0];
                oacc[mf][nf][1] *= corr[nf][1];
                oacc[mf][nf][2] *= corr[nf][0];
                oacc[mf][nf][3] *= corr[nf][1];
            }

        __syncthreads();   // all warps done reading Ks: Ps may alias it

        // ---- Store P^T (tf32) to warp-private smem ----
        #pragma unroll
        for (int mf = 0; mf < 4; mf++)
            #pragma unroll
            for (int nf = 0; nf < 2; nf++)
                #pragma unroll
                for (int j = 0; j < 4; j++) {
                    const int key = mf * 16 + r + 8 * (j >> 1);
                    const int q   = nf * 8 + 2 * c + (j & 1);
                    Psw[key * 24 + q] = cvt_tf32(sacc[mf][nf][j]);
                }
        __syncwarp();

        // ---- O^T += V^T @ P^T ----
        #pragma unroll
        for (int kk = 0; kk < 8; kk++) {
            uint32_t bf[2][2];
            #pragma unroll
            for (int nf = 0; nf < 2; nf++) {
                bf[nf][0] = Psw[(kk * 8 + c) * 24 + nf * 8 + r];
                bf[nf][1] = Psw[(kk * 8 + c + 4) * 24 + nf * 8 + r];
            }
            uint32_t af[4][4];
            #pragma unroll
            for (int mf = 0; mf < 4; mf++) {
                const int d = mf * 16 + r;
                af[mf][0] = Vs[(kk * 8 + c) * 72 + d];
                af[mf][1] = Vs[(kk * 8 + c) * 72 + d + 8];
                af[mf][2] = Vs[(kk * 8 + c + 4) * 72 + d];
                af[mf][3] = Vs[(kk * 8 + c + 4) * 72 + d + 8];
            }
            #pragma unroll
            for (int mf = 0; mf < 4; mf++) {
                mma_tf32(oacc[mf][0], af[mf], bf[0]);
                mma_tf32(oacc[mf][1], af[mf], bf[1]);
            }
        }
        __syncthreads();   // protect Ks/Ps/Vs before next tile's stores
    }

    // ---- Epilogue: normalize, write [B,S,E] ----
    const int b = bh >> 4, h = bh & 15;
    float inv[2][2];
    #pragma unroll
    for (int nf = 0; nf < 2; nf++)
        #pragma unroll
        for (int hh = 0; hh < 2; hh++) inv[nf][hh] = 1.0f / l_s[nf][hh];

    #pragma unroll
    for (int mf = 0; mf < 4; mf++)
        #pragma unroll
        for (int nf = 0; nf < 2; nf++)
            #pragma unroll
            for (int j = 0; j < 4; j++) {
                const int d = mf * 16 + r + 8 * (j >> 1);
                const int q = qb * 64 + w * 16 + nf * 8 + 2 * c + (j & 1);
                g_O[((size_t)(b * SEQ + q)) * EMB + h * HD + d] =
                    oacc[mf][nf][j] * inv[nf][j & 1];
            }
}

// ---------------------------------------------------------------------------
extern "C" void kernel_launch(void* const* d_in, const int* in_sizes, int n_in,
                              void* d_out, int out_size)
{
    const float* x  = (const float*)d_in[0];
    const float* Wq = (const float*)d_in[1];
    const float* bq = (const float*)d_in[2];
    const float* Wk = (const float*)d_in[3];
    const float* bk = (const float*)d_in[4];
    const float* Wv = (const float*)d_in[5];
    const float* bv = (const float*)d_in[6];
    const float* Wo = (const float*)d_in[7];
    const float* bo = (const float*)d_in[8];
    float* out = (float*)d_out;

    // 1) QKV projections (tf32 mma.sync) -> head-major scratch
    qkv_gemm_kernel<<<dim3(EMB / 128, MROWS / 128, 3), 256>>>(
        x, Wq, bq, Wk, bk, Wv, bv);

    // 2) Flash attention (tf32 mma.sync) -> g_O [B,S,E]
    attn_kernel<<<dim3(SEQ / 64, BATCH * NH), 128>>>();

    // 3) Output projection (tf32 mma.sync) -> d_out
    proj_gemm_kernel<<<dim3(EMB / 128, MROWS / 128), 256>>>(Wo, bo, out);
}

// round 10
// speedup vs baseline: 3.4061x; 1.2309x over previous
#include <cuda_runtime.h>
#include <cstdint>

// Problem constants (fixed by the reference)
#define BATCH 2
#define SEQ   2048
#define EMB   1024
#define NH    16
#define HD    64
#define MROWS (BATCH * SEQ)   // 4096

// Scratch (device globals — no allocation allowed)
__device__ float g_Q[BATCH * NH * SEQ * HD];  // [B,H,S,D]
__device__ float g_K[BATCH * NH * SEQ * HD];
__device__ float g_V[BATCH * NH * SEQ * HD];
__device__ float g_O[BATCH * SEQ * EMB];      // [B,S,E] (heads concatenated)

// ---------------------------------------------------------------------------
// mma.sync tf32 helpers (plain sm_103 — no 'a'-feature instructions)
// ---------------------------------------------------------------------------
__device__ __forceinline__ uint32_t cvt_tf32(float f) {
    uint32_t r;
    asm("cvt.rna.tf32.f32 %0, %1;" : "=r"(r) : "f"(f));
    return r;
}

// D(16x8,f32) += A(16x8,tf32) * B(8x8,tf32)
__device__ __forceinline__ void mma_tf32(float* d, const uint32_t* a,
                                         const uint32_t* b) {
    asm volatile(
        "mma.sync.aligned.m16n8k8.row.col.f32.tf32.tf32.f32 "
        "{%0,%1,%2,%3}, {%4,%5,%6,%7}, {%8,%9}, {%0,%1,%2,%3};"
        : "+f"(d[0]), "+f"(d[1]), "+f"(d[2]), "+f"(d[3])
        : "r"(a[0]), "r"(a[1]), "r"(a[2]), "r"(a[3]),
          "r"(b[0]), "r"(b[1]));
}

__device__ __forceinline__ uint32_t smem_u32(const void* p) {
    uint32_t a;
    asm("{ .reg .u64 t; cvta.to.shared.u64 t, %1; cvt.u32.u64 %0, t; }"
        : "=r"(a) : "l"(p));
    return a;
}

__device__ __forceinline__ void cp_async16(uint32_t dst, const void* src) {
    asm volatile("cp.async.cg.shared.global [%0], [%1], 16;"
                 :: "r"(dst), "l"(src) : "memory");
}
__device__ __forceinline__ void cp_commit() {
    asm volatile("cp.async.commit_group;" ::: "memory");
}
__device__ __forceinline__ void cp_wait0() {
    asm volatile("cp.async.wait_group 0;" ::: "memory");
}

// ---------------------------------------------------------------------------
// tf32 warp-MMA GEMM: out = A[4096x1024] @ W[1024x1024] + bias
// BM=BN=128, BK=16, 64 K-steps, double-buffered smem fed by cp.async.
// 256 threads = 8 warps (4m x 2n), warp tile 32m x 64n.
// Operands are raw fp32 bits consumed as tf32 (HW truncates low mantissa).
// Smem strides: As[.][m][20w] (bank = 20r+c: conflict-free frag loads),
//               Bs[.][k][136w] (bank = 8c+8nf+r: conflict-free).
// MODE 0: scatter to head-major [B,H,S,D]; MODE 1: plain [M,N].
// ---------------------------------------------------------------------------
#define AS_STRIDE 20
#define BS_STRIDE 136
#define AS_BUF (128 * AS_STRIDE)     // words per A buffer (10240 B)
#define BS_BUF (16 * BS_STRIDE)      // words per B buffer (8704 B)

template <int MODE>
__device__ __forceinline__ void mma_gemm_body(const float* __restrict__ A,
                                              const float* __restrict__ W,
                                              const float* __restrict__ bias,
                                              float* __restrict__ out)
{
    __shared__ __align__(16) uint32_t As[2][128][AS_STRIDE];   // 20480 B
    __shared__ __align__(16) uint32_t Bs[2][16][BS_STRIDE];    // 17408 B

    const int tid  = threadIdx.x;
    const int lane = tid & 31;
    const int wid  = tid >> 5;
    const int wm   = wid >> 1;
    const int wn   = wid & 1;
    const int m0   = blockIdx.y * 128;
    const int n0   = blockIdx.x * 128;

    const uint32_t as_base = smem_u32(&As[0][0][0]);
    const uint32_t bs_base = smem_u32(&Bs[0][0][0]);

    // cp.async maps (16B chunks)
    const int ar = tid >> 2;             // A rows ar, ar+64
    const int ac = (tid & 3) * 4;        // A word col {0,4,8,12}
    const int br = tid >> 5;             // B rows br, br+8
    const int bc = (tid & 31) * 4;       // B word col

    const float* Abase = A + (size_t)(m0 + ar) * EMB + ac;
    const float* Wbase = W + (size_t)br * EMB + n0 + bc;
    const uint32_t a_dst0 = as_base + (uint32_t)(ar * AS_STRIDE + ac) * 4u;
    const uint32_t a_dst1 = a_dst0 + 64u * AS_STRIDE * 4u;
    const uint32_t b_dst0 = bs_base + (uint32_t)(br * BS_STRIDE + bc) * 4u;
    const uint32_t b_dst1 = b_dst0 + 8u * BS_STRIDE * 4u;

    float acc[2][8][4];
    #pragma unroll
    for (int mf = 0; mf < 2; mf++)
        #pragma unroll
        for (int nf = 0; nf < 8; nf++)
            #pragma unroll
            for (int j = 0; j < 4; j++) acc[mf][nf][j] = 0.0f;

    const int r = lane >> 2;
    const int c = lane & 3;

    // Prologue: stage 0 -> buffer 0
    {
        cp_async16(a_dst0, Abase);
        cp_async16(a_dst1, Abase + (size_t)64 * EMB);
        cp_async16(b_dst0, Wbase);
        cp_async16(b_dst1, Wbase + (size_t)8 * EMB);
        cp_commit();
    }

    for (int it = 0; it < 64; ++it) {
        const int p = it & 1;
        cp_wait0();
        __syncthreads();

        // Issue next stage into the other buffer (overlaps with compute below)
        if (it + 1 < 64) {
            const uint32_t boff_a = (uint32_t)((p ^ 1) * AS_BUF) * 4u;
            const uint32_t boff_b = (uint32_t)((p ^ 1) * BS_BUF) * 4u;
            const int k0 = (it + 1) * 16;
            cp_async16(a_dst0 + boff_a, Abase + k0);
            cp_async16(a_dst1 + boff_a, Abase + (size_t)64 * EMB + k0);
            cp_async16(b_dst0 + boff_b, Wbase + (size_t)k0 * EMB);
            cp_async16(b_dst1 + boff_b, Wbase + (size_t)(k0 + 8) * EMB);
            cp_commit();
        }

        const uint32_t* Ap = &As[p][0][0];
        const uint32_t* Bp = &Bs[p][0][0];

        #pragma unroll
        for (int ks = 0; ks < 2; ks++) {
            const int kk = ks * 8;
            uint32_t af[2][4];
            #pragma unroll
            for (int mf = 0; mf < 2; mf++) {
                const int m = wm * 32 + mf * 16 + r;
                af[mf][0] = Ap[m * AS_STRIDE + kk + c];
                af[mf][1] = Ap[(m + 8) * AS_STRIDE + kk + c];
                af[mf][2] = Ap[m * AS_STRIDE + kk + c + 4];
                af[mf][3] = Ap[(m + 8) * AS_STRIDE + kk + c + 4];
            }
            #pragma unroll
            for (int nf = 0; nf < 8; nf++) {
                const int n = wn * 64 + nf * 8 + r;
                uint32_t bf[2];
                bf[0] = Bp[(kk + c) * BS_STRIDE + n];
                bf[1] = Bp[(kk + c + 4) * BS_STRIDE + n];
                mma_tf32(acc[0][nf], af[0], bf);
                mma_tf32(acc[1][nf], af[1], bf);
            }
        }
    }

    // Epilogue: bias add + store.
    const int c2 = (lane & 3) * 2;
    #pragma unroll
    for (int mf = 0; mf < 2; mf++) {
        const int row0 = m0 + wm * 32 + mf * 16 + r;
        #pragma unroll
        for (int nf = 0; nf < 8; nf++) {
            const int col = n0 + wn * 64 + nf * 8 + c2;
            const float b0 = bias[col], b1 = bias[col + 1];
            float2 v0, v1;
            v0.x = acc[mf][nf][0] + b0; v0.y = acc[mf][nf][1] + b1;
            v1.x = acc[mf][nf][2] + b0; v1.y = acc[mf][nf][3] + b1;
            if (MODE == 0) {
                const int h = col >> 6, d = col & 63;
                {
                    const int b = row0 >> 11, s = row0 & 2047;
                    *(float2*)&out[((size_t)((b << 4) + h) * SEQ + s) * HD + d] = v0;
                }
                {
                    const int row1 = row0 + 8;
                    const int b = row1 >> 11, s = row1 & 2047;
                    *(float2*)&out[((size_t)((b << 4) + h) * SEQ + s) * HD + d] = v1;
                }
            } else {
                *(float2*)&out[(size_t)row0 * EMB + col] = v0;
                *(float2*)&out[(size_t)(row0 + 8) * EMB + col] = v1;
            }
        }
    }
}

__global__ __launch_bounds__(256, 2)
void qkv_gemm_kernel(const float* __restrict__ x,
                     const float* __restrict__ Wq, const float* __restrict__ bq,
                     const float* __restrict__ Wk, const float* __restrict__ bk,
                     const float* __restrict__ Wv, const float* __restrict__ bv)
{
    const float* W; const float* bias; float* out;
    if (blockIdx.z == 0)      { W = Wq; bias = bq; out = g_Q; }
    else if (blockIdx.z == 1) { W = Wk; bias = bk; out = g_K; }
    else                      { W = Wv; bias = bv; out = g_V; }
    mma_gemm_body<0>(x, W, bias, out);
}

__global__ __launch_bounds__(256, 2)
void proj_gemm_kernel(const float* __restrict__ Wo,
                      const float* __restrict__ bo,
                      float* __restrict__ out)
{
    mma_gemm_body<1>(g_O, Wo, bo, out);
}

// ---------------------------------------------------------------------------
// Tensor-core flash attention (tf32 mma.sync) — unchanged from R5 (passing).
// ---------------------------------------------------------------------------
__global__ __launch_bounds__(128, 4)
void attn_kernel()
{
    __shared__ __align__(16) uint32_t SM[10752];
    uint32_t* const Ks = SM;            // [key*72 + d], tf32
    uint32_t* const Vs = SM + 6144;     // [key*72 + d], tf32

    const int tid  = threadIdx.x;
    const int lane = tid & 31;
    const int w    = tid >> 5;
    const int r    = lane >> 2;   // 0..7
    const int c    = lane & 3;    // 0..3
    const int qb   = blockIdx.x;  // 0..31
    const int bh   = blockIdx.y;  // 0..31

    uint32_t* const Psw = SM + w * 1536;   // warp-private P^T [key*24 + q]

    const float* Qbase = g_Q + (size_t)bh * SEQ * HD + (size_t)qb * 64 * HD;
    const float* Kbase = g_K + (size_t)bh * SEQ * HD;
    const float* Vbase = g_V + (size_t)bh * SEQ * HD;

    const int lrow = tid >> 4;           // 0..7
    const int lcol = (tid & 15) * 4;     // 0..60

    // ---- Stage Q (raw fp32) into Vs, extract B-fragments (scaled, tf32) ----
    #pragma unroll
    for (int p = 0; p < 8; p++) {
        const int row = p * 8 + lrow;
        *(float4*)&Vs[row * 72 + lcol] =
            *(const float4*)&Qbase[(size_t)row * HD + lcol];
    }
    __syncthreads();

    uint32_t qf[8][2][2];   // [k-oct][nf][b0/b1]
    #pragma unroll
    for (int ks = 0; ks < 8; ks++)
        #pragma unroll
        for (int nf = 0; nf < 2; nf++) {
            const int q = w * 16 + nf * 8 + r;
            qf[ks][nf][0] =
                cvt_tf32(__uint_as_float(Vs[q * 72 + ks * 8 + c]) * 0.125f);
            qf[ks][nf][1] =
                cvt_tf32(__uint_as_float(Vs[q * 72 + ks * 8 + c + 4]) * 0.125f);
        }
    __syncthreads();

    float oacc[4][2][4];    // O^T frags: [d-oct(16)][q-nf][4]
    #pragma unroll
    for (int mf = 0; mf < 4; mf++)
        #pragma unroll
        for (int nf = 0; nf < 2; nf++)
            #pragma unroll
            for (int j = 0; j < 4; j++) oacc[mf][nf][j] = 0.0f;

    float m_s[2][2], l_s[2][2];
    #pragma unroll
    for (int nf = 0; nf < 2; nf++)
        #pragma unroll
        for (int h = 0; h < 2; h++) { m_s[nf][h] = -1e30f; l_s[nf][h] = 0.0f; }

    for (int kt = 0; kt < SEQ; kt += 64) {
        // ---- Load K, V tiles (tf32, natural row layout) ----
        #pragma unroll
        for (int p = 0; p < 8; p++) {
            const int row = p * 8 + lrow;
            float4 kv = *(const float4*)&Kbase[(size_t)(kt + row) * HD + lcol];
            uint4 kp;
            kp.x = cvt_tf32(kv.x); kp.y = cvt_tf32(kv.y);
            kp.z = cvt_tf32(kv.z); kp.w = cvt_tf32(kv.w);
            *(uint4*)&Ks[row * 72 + lcol] = kp;
            float4 vv = *(const float4*)&Vbase[(size_t)(kt + row) * HD + lcol];
            uint4 vp;
            vp.x = cvt_tf32(vv.x); vp.y = cvt_tf32(vv.y);
            vp.z = cvt_tf32(vv.z); vp.w = cvt_tf32(vv.w);
            *(uint4*)&Vs[row * 72 + lcol] = vp;
        }
        __syncthreads();

        // ---- S^T = K @ Q^T : frags [key 64][q 16] ----
        float sacc[4][2][4];
        #pragma unroll
        for (int mf = 0; mf < 4; mf++)
            #pragma unroll
            for (int nf = 0; nf < 2; nf++)
                #pragma unroll
                for (int j = 0; j < 4; j++) sacc[mf][nf][j] = 0.0f;

        #pragma unroll
        for (int ks = 0; ks < 8; ks++) {
            uint32_t af[4][4];
            #pragma unroll
            for (int mf = 0; mf < 4; mf++) {
                const int m = mf * 16 + r;
                af[mf][0] = Ks[m * 72 + ks * 8 + c];
                af[mf][1] = Ks[(m + 8) * 72 + ks * 8 + c];
                af[mf][2] = Ks[m * 72 + ks * 8 + c + 4];
                af[mf][3] = Ks[(m + 8) * 72 + ks * 8 + c + 4];
            }
            #pragma unroll
            for (int mf = 0; mf < 4; mf++) {
                mma_tf32(sacc[mf][0], af[mf], qf[ks][0]);
                mma_tf32(sacc[mf][1], af[mf], qf[ks][1]);
            }
        }

        // ---- Online softmax (key-dim reduction: in-thread + shfl over r) ----
        float corr[2][2];
        #pragma unroll
        for (int nf = 0; nf < 2; nf++)
            #pragma unroll
            for (int h = 0; h < 2; h++) {
                float mx = -1e30f;
                #pragma unroll
                for (int mf = 0; mf < 4; mf++)
                    mx = fmaxf(mx, fmaxf(sacc[mf][nf][h], sacc[mf][nf][h + 2]));
                mx = fmaxf(mx, __shfl_xor_sync(0xffffffffu, mx, 4));
                mx = fmaxf(mx, __shfl_xor_sync(0xffffffffu, mx, 8));
                mx = fmaxf(mx, __shfl_xor_sync(0xffffffffu, mx, 16));
                const float mn = fmaxf(m_s[nf][h], mx);
                corr[nf][h] = __expf(m_s[nf][h] - mn);
                m_s[nf][h] = mn;
            }
        #pragma unroll
        for (int mf = 0; mf < 4; mf++)
            #pragma unroll
            for (int nf = 0; nf < 2; nf++) {
                sacc[mf][nf][0] = __expf(sacc[mf][nf][0] - m_s[nf][0]);
                sacc[mf][nf][1] = __expf(sacc[mf][nf][1] - m_s[nf][1]);
                sacc[mf][nf][2] = __expf(sacc[mf][nf][2] - m_s[nf][0]);
                sacc[mf][nf][3] = __expf(sacc[mf][nf][3] - m_s[nf][1]);
            }
        #pragma unroll
        for (int nf = 0; nf < 2; nf++)
            #pragma unroll
            for (int h = 0; h < 2; h++) {
                float sm = 0.0f;
                #pragma unroll
                for (int mf = 0; mf < 4; mf++)
                    sm += sacc[mf][nf][h] + sacc[mf][nf][h + 2];
                sm += __shfl_xor_sync(0xffffffffu, sm, 4);
                sm += __shfl_xor_sync(0xffffffffu, sm, 8);
                sm += __shfl_xor_sync(0xffffffffu, sm, 16);
                l_s[nf][h] = l_s[nf][h] * corr[nf][h] + sm;
            }
        #pragma unroll
        for (int mf = 0; mf < 4; mf++)
            #pragma unroll
            for (int nf = 0; nf < 2; nf++) {
                oacc[mf][nf][0] *= corr[nf][0];
                oacc[mf][nf][1] *= corr[nf][1];
                oacc[mf][nf][2] *= corr[nf][0];
                oacc[mf][nf][3] *= corr[nf][1];
            }

        __syncthreads();   // all warps done reading Ks: Ps may alias it

        // ---- Store P^T (tf32) to warp-private smem ----
        #pragma unroll
        for (int mf = 0; mf < 4; mf++)
            #pragma unroll
            for (int nf = 0; nf < 2; nf++)
                #pragma unroll
                for (int j = 0; j < 4; j++) {
                    const int key = mf * 16 + r + 8 * (j >> 1);
                    const int q   = nf * 8 + 2 * c + (j & 1);
                    Psw[key * 24 + q] = cvt_tf32(sacc[mf][nf][j]);
                }
        __syncwarp();

        // ---- O^T += V^T @ P^T ----
        #pragma unroll
        for (int kk = 0; kk < 8; kk++) {
            uint32_t bf[2][2];
            #pragma unroll
            for (int nf = 0; nf < 2; nf++) {
                bf[nf][0] = Psw[(kk * 8 + c) * 24 + nf * 8 + r];
                bf[nf][1] = Psw[(kk * 8 + c + 4) * 24 + nf * 8 + r];
            }
            uint32_t af[4][4];
            #pragma unroll
            for (int mf = 0; mf < 4; mf++) {
                const int d = mf * 16 + r;
                af[mf][0] = Vs[(kk * 8 + c) * 72 + d];
                af[mf][1] = Vs[(kk * 8 + c) * 72 + d + 8];
                af[mf][2] = Vs[(kk * 8 + c + 4) * 72 + d];
                af[mf][3] = Vs[(kk * 8 + c + 4) * 72 + d + 8];
            }
            #pragma unroll
            for (int mf = 0; mf < 4; mf++) {
                mma_tf32(oacc[mf][0], af[mf], bf[0]);
                mma_tf32(oacc[mf][1], af[mf], bf[1]);
            }
        }
        __syncthreads();   // protect Ks/Ps/Vs before next tile's stores
    }

    // ---- Epilogue: normalize, write [B,S,E] ----
    const int b = bh >> 4, h = bh & 15;
    float inv[2][2];
    #pragma unroll
    for (int nf = 0; nf < 2; nf++)
        #pragma unroll
        for (int hh = 0; hh < 2; hh++) inv[nf][hh] = 1.0f / l_s[nf][hh];

    #pragma unroll
    for (int mf = 0; mf < 4; mf++)
        #pragma unroll
        for (int nf = 0; nf < 2; nf++)
            #pragma unroll
            for (int j = 0; j < 4; j++) {
                const int d = mf * 16 + r + 8 * (j >> 1);
                const int q = qb * 64 + w * 16 + nf * 8 + 2 * c + (j & 1);
                g_O[((size_t)(b * SEQ + q)) * EMB + h * HD + d] =
                    oacc[mf][nf][j] * inv[nf][j & 1];
            }
}

// ---------------------------------------------------------------------------
extern "C" void kernel_launch(void* const* d_in, const int* in_sizes, int n_in,
                              void* d_out, int out_size)
{
    const float* x  = (const float*)d_in[0];
    const float* Wq = (const float*)d_in[1];
    const float* bq = (const float*)d_in[2];
    const float* Wk = (const float*)d_in[3];
    const float* bk = (const float*)d_in[4];
    const float* Wv = (const float*)d_in[5];
    const float* bv = (const float*)d_in[6];
    const float* Wo = (const float*)d_in[7];
    const float* bo = (const float*)d_in[8];
    float* out = (float*)d_out;

    // 1) QKV projections (tf32 mma.sync + cp.async pipeline) -> head-major
    qkv_gemm_kernel<<<dim3(EMB / 128, MROWS / 128, 3), 256>>>(
        x, Wq, bq, Wk, bk, Wv, bv);

    // 2) Flash attention (tf32 mma.sync) -> g_O [B,S,E]
    attn_kernel<<<dim3(SEQ / 64, BATCH * NH), 128>>>();

    // 3) Output projection (tf32 mma.sync + cp.async pipeline) -> d_out
    proj_gemm_kernel<<<dim3(EMB / 128, MROWS / 128), 256>>>(Wo, bo, out);
}

// round 14
// speedup vs baseline: 3.5166x; 1.0324x over previous
#include <cuda_runtime.h>
#include <cstdint>

// Problem constants (fixed by the reference)
#define BATCH 2
#define SEQ   2048
#define EMB   1024
#define NH    16
#define HD    64
#define MROWS (BATCH * SEQ)   // 4096

// Scratch (device globals — no allocation allowed)
__device__ float g_Q[BATCH * NH * SEQ * HD];  // [B,H,S,D]
__device__ float g_K[BATCH * NH * SEQ * HD];
__device__ float g_V[BATCH * NH * SEQ * HD];
__device__ float g_O[BATCH * SEQ * EMB];      // [B,S,E] (heads concatenated)

// ---------------------------------------------------------------------------
// mma.sync tf32 helpers (plain sm_103 — no 'a'-feature instructions)
// ---------------------------------------------------------------------------
__device__ __forceinline__ uint32_t cvt_tf32(float f) {
    uint32_t r;
    asm("cvt.rna.tf32.f32 %0, %1;" : "=r"(r) : "f"(f));
    return r;
}

// D(16x8,f32) += A(16x8,tf32) * B(8x8,tf32)
__device__ __forceinline__ void mma_tf32(float* d, const uint32_t* a,
                                         const uint32_t* b) {
    asm volatile(
        "mma.sync.aligned.m16n8k8.row.col.f32.tf32.tf32.f32 "
        "{%0,%1,%2,%3}, {%4,%5,%6,%7}, {%8,%9}, {%0,%1,%2,%3};"
        : "+f"(d[0]), "+f"(d[1]), "+f"(d[2]), "+f"(d[3])
        : "r"(a[0]), "r"(a[1]), "r"(a[2]), "r"(a[3]),
          "r"(b[0]), "r"(b[1]));
}

__device__ __forceinline__ uint32_t smem_u32(const void* p) {
    uint32_t a;
    asm("{ .reg .u64 t; cvta.to.shared.u64 t, %1; cvt.u32.u64 %0, t; }"
        : "=r"(a) : "l"(p));
    return a;
}

__device__ __forceinline__ void cp_async16(uint32_t dst, const void* src) {
    asm volatile("cp.async.cg.shared.global [%0], [%1], 16;"
                 :: "r"(dst), "l"(src) : "memory");
}
__device__ __forceinline__ void cp_commit() {
    asm volatile("cp.async.commit_group;" ::: "memory");
}
__device__ __forceinline__ void cp_wait0() {
    asm volatile("cp.async.wait_group 0;" ::: "memory");
}

// Round fp32 bit-pattern to nearest tf32 (HW truncates the low 13 bits,
// so +0x1000 implements round-half-up; carry into exponent is correct).
#define TF32_RND 0x1000u

// ---------------------------------------------------------------------------
// tf32 warp-MMA GEMM: out = A[4096x1024] @ W[1024x1024] + bias
// BM=BN=128, BK=16, 64 K-steps, double-buffered smem fed by cp.async.
// 256 threads = 8 warps (4m x 2n), warp tile 32m x 64n.
// Operand bits rounded (+0x1000) at fragment load -> effective cvt.rna.
// MODE 0: scatter to head-major [B,H,S,D]; MODE 1: plain [M,N].
// ---------------------------------------------------------------------------
#define AS_STRIDE 20
#define BS_STRIDE 136
#define AS_BUF (128 * AS_STRIDE)     // words per A buffer (10240 B)
#define BS_BUF (16 * BS_STRIDE)      // words per B buffer (8704 B)

template <int MODE>
__device__ __forceinline__ void mma_gemm_body(const float* __restrict__ A,
                                              const float* __restrict__ W,
                                              const float* __restrict__ bias,
                                              float* __restrict__ out)
{
    __shared__ __align__(16) uint32_t As[2][128][AS_STRIDE];   // 20480 B
    __shared__ __align__(16) uint32_t Bs[2][16][BS_STRIDE];    // 17408 B

    const int tid  = threadIdx.x;
    const int lane = tid & 31;
    const int wid  = tid >> 5;
    const int wm   = wid >> 1;
    const int wn   = wid & 1;
    const int m0   = blockIdx.y * 128;
    const int n0   = blockIdx.x * 128;

    const uint32_t as_base = smem_u32(&As[0][0][0]);
    const uint32_t bs_base = smem_u32(&Bs[0][0][0]);

    // cp.async maps (16B chunks)
    const int ar = tid >> 2;             // A rows ar, ar+64
    const int ac = (tid & 3) * 4;        // A word col {0,4,8,12}
    const int br = tid >> 5;             // B rows br, br+8
    const int bc = (tid & 31) * 4;       // B word col

    const float* Abase = A + (size_t)(m0 + ar) * EMB + ac;
    const float* Wbase = W + (size_t)br * EMB + n0 + bc;
    const uint32_t a_dst0 = as_base + (uint32_t)(ar * AS_STRIDE + ac) * 4u;
    const uint32_t a_dst1 = a_dst0 + 64u * AS_STRIDE * 4u;
    const uint32_t b_dst0 = bs_base + (uint32_t)(br * BS_STRIDE + bc) * 4u;
    const uint32_t b_dst1 = b_dst0 + 8u * BS_STRIDE * 4u;

    float acc[2][8][4];
    #pragma unroll
    for (int mf = 0; mf < 2; mf++)
        #pragma unroll
        for (int nf = 0; nf < 8; nf++)
            #pragma unroll
            for (int j = 0; j < 4; j++) acc[mf][nf][j] = 0.0f;

    const int r = lane >> 2;
    const int c = lane & 3;

    // Prologue: stage 0 -> buffer 0
    {
        cp_async16(a_dst0, Abase);
        cp_async16(a_dst1, Abase + (size_t)64 * EMB);
        cp_async16(b_dst0, Wbase);
        cp_async16(b_dst1, Wbase + (size_t)8 * EMB);
        cp_commit();
    }

    for (int it = 0; it < 64; ++it) {
        const int p = it & 1;
        cp_wait0();
        __syncthreads();

        // Issue next stage into the other buffer (overlaps with compute below)
        if (it + 1 < 64) {
            const uint32_t boff_a = (uint32_t)((p ^ 1) * AS_BUF) * 4u;
            const uint32_t boff_b = (uint32_t)((p ^ 1) * BS_BUF) * 4u;
            const int k0 = (it + 1) * 16;
            cp_async16(a_dst0 + boff_a, Abase + k0);
            cp_async16(a_dst1 + boff_a, Abase + (size_t)64 * EMB + k0);
            cp_async16(b_dst0 + boff_b, Wbase + (size_t)k0 * EMB);
            cp_async16(b_dst1 + boff_b, Wbase + (size_t)(k0 + 8) * EMB);
            cp_commit();
        }

        const uint32_t* Ap = &As[p][0][0];
        const uint32_t* Bp = &Bs[p][0][0];

        #pragma unroll
        for (int ks = 0; ks < 2; ks++) {
            const int kk = ks * 8;
            uint32_t af[2][4];
            #pragma unroll
            for (int mf = 0; mf < 2; mf++) {
                const int m = wm * 32 + mf * 16 + r;
                af[mf][0] = Ap[m * AS_STRIDE + kk + c] + TF32_RND;
                af[mf][1] = Ap[(m + 8) * AS_STRIDE + kk + c] + TF32_RND;
                af[mf][2] = Ap[m * AS_STRIDE + kk + c + 4] + TF32_RND;
                af[mf][3] = Ap[(m + 8) * AS_STRIDE + kk + c + 4] + TF32_RND;
            }
            #pragma unroll
            for (int nf = 0; nf < 8; nf++) {
                const int n = wn * 64 + nf * 8 + r;
                uint32_t bf[2];
                bf[0] = Bp[(kk + c) * BS_STRIDE + n] + TF32_RND;
                bf[1] = Bp[(kk + c + 4) * BS_STRIDE + n] + TF32_RND;
                mma_tf32(acc[0][nf], af[0], bf);
                mma_tf32(acc[1][nf], af[1], bf);
            }
        }
    }

    // Epilogue: bias add + store.
    const int c2 = (lane & 3) * 2;
    #pragma unroll
    for (int mf = 0; mf < 2; mf++) {
        const int row0 = m0 + wm * 32 + mf * 16 + r;
        #pragma unroll
        for (int nf = 0; nf < 8; nf++) {
            const int col = n0 + wn * 64 + nf * 8 + c2;
            const float b0 = bias[col], b1 = bias[col + 1];
            float2 v0, v1;
            v0.x = acc[mf][nf][0] + b0; v0.y = acc[mf][nf][1] + b1;
            v1.x = acc[mf][nf][2] + b0; v1.y = acc[mf][nf][3] + b1;
            if (MODE == 0) {
                const int h = col >> 6, d = col & 63;
                {
                    const int b = row0 >> 11, s = row0 & 2047;
                    *(float2*)&out[((size_t)((b << 4) + h) * SEQ + s) * HD + d] = v0;
                }
                {
                    const int row1 = row0 + 8;
                    const int b = row1 >> 11, s = row1 & 2047;
                    *(float2*)&out[((size_t)((b << 4) + h) * SEQ + s) * HD + d] = v1;
                }
            } else {
                *(float2*)&out[(size_t)row0 * EMB + col] = v0;
                *(float2*)&out[(size_t)(row0 + 8) * EMB + col] = v1;
            }
        }
    }
}

__global__ __launch_bounds__(256, 2)
void qkv_gemm_kernel(const float* __restrict__ x,
                     const float* __restrict__ Wq, const float* __restrict__ bq,
                     const float* __restrict__ Wk, const float* __restrict__ bk,
                     const float* __restrict__ Wv, const float* __restrict__ bv)
{
    const float* W; const float* bias; float* out;
    if (blockIdx.z == 0)      { W = Wq; bias = bq; out = g_Q; }
    else if (blockIdx.z == 1) { W = Wk; bias = bk; out = g_K; }
    else                      { W = Wv; bias = bv; out = g_V; }
    mma_gemm_body<0>(x, W, bias, out);
}

__global__ __launch_bounds__(256, 2)
void proj_gemm_kernel(const float* __restrict__ Wo,
                      const float* __restrict__ bo,
                      float* __restrict__ out)
{
    mma_gemm_body<1>(g_O, Wo, bo, out);
}

// ---------------------------------------------------------------------------
// Tensor-core flash attention (tf32 mma.sync), non-transposed formulation.
// Grid (32 q-blocks, 32 b*h), 128 threads = 4 warps; warp w owns queries
// [w*16, w*16+16), all 64 keys per tile.
// S = Q@K^T (m=q, n=key, k=d): Q persistent A-frags, K B-frags from smem.
// O = P@V  (m=q, n=d,  k=key): P A-frags built from S d-frags via shfl
// (no P smem round-trip), V B-frags from smem.
// Smem strides: Ks stride 68 (68%32=4 -> K b-frag bank 4r+c, conflict-free),
//               Vs stride 72 (72%32=8 -> V b-frag bank 8c+r, conflict-free).
// ---------------------------------------------------------------------------
#define KST 68
#define VST 72

__global__ __launch_bounds__(128, 4)
void attn_kernel()
{
    __shared__ __align__(16) uint32_t SM[64 * KST + 64 * VST];  // 35840 B
    uint32_t* const Ks = SM;              // [key*KST + d], tf32
    uint32_t* const Vs = SM + 64 * KST;   // [key*VST + d], tf32

    const int tid  = threadIdx.x;
    const int lane = tid & 31;
    const int w    = tid >> 5;
    const int r    = lane >> 2;   // 0..7
    const int c    = lane & 3;    // 0..3
    const int qb   = blockIdx.x;  // 0..31
    const int bh   = blockIdx.y;  // 0..31

    const float* Qbase = g_Q + (size_t)bh * SEQ * HD + (size_t)qb * 64 * HD;
    const float* Kbase = g_K + (size_t)bh * SEQ * HD;
    const float* Vbase = g_V + (size_t)bh * SEQ * HD;

    const int lrow = tid >> 4;           // 0..7
    const int lcol = (tid & 15) * 4;     // 0..60

    // ---- Stage Q (raw fp32) into Ks, extract A-fragments (scaled, tf32) ----
    #pragma unroll
    for (int p = 0; p < 8; p++) {
        const int row = p * 8 + lrow;
        *(float4*)&Ks[row * KST + lcol] =
            *(const float4*)&Qbase[(size_t)row * HD + lcol];
    }
    __syncthreads();

    uint32_t qf[8][4];   // A-frags: [k-oct][a0..a3], rows w*16+r / +8
    #pragma unroll
    for (int ks = 0; ks < 8; ks++) {
        const int base = (w * 16 + r) * KST + ks * 8 + c;
        qf[ks][0] = cvt_tf32(__uint_as_float(Ks[base]) * 0.125f);
        qf[ks][1] = cvt_tf32(__uint_as_float(Ks[base + 8 * KST]) * 0.125f);
        qf[ks][2] = cvt_tf32(__uint_as_float(Ks[base + 4]) * 0.125f);
        qf[ks][3] = cvt_tf32(__uint_as_float(Ks[base + 8 * KST + 4]) * 0.125f);
    }
    __syncthreads();

    float oacc[8][4];    // O d-frags: [d-tile][d0..d3] rows r/r+8, cols 2c,2c+1
    #pragma unroll
    for (int nt = 0; nt < 8; nt++)
        #pragma unroll
        for (int j = 0; j < 4; j++) oacc[nt][j] = 0.0f;

    float m0 = -1e30f, m1 = -1e30f, l0 = 0.0f, l1 = 0.0f;

    // shfl source lanes for P d-frag -> a-frag rearrangement
    const int s1l = (lane & ~3) | (c >> 1);
    const int s2l = s1l + 2;
    const bool codd = (c & 1) != 0;

    for (int kt = 0; kt < SEQ; kt += 64) {
        // ---- Load K, V tiles (tf32, natural row layout) ----
        #pragma unroll
        for (int p = 0; p < 8; p++) {
            const int row = p * 8 + lrow;
            float4 kv = *(const float4*)&Kbase[(size_t)(kt + row) * HD + lcol];
            uint4 kp;
            kp.x = cvt_tf32(kv.x); kp.y = cvt_tf32(kv.y);
            kp.z = cvt_tf32(kv.z); kp.w = cvt_tf32(kv.w);
            *(uint4*)&Ks[row * KST + lcol] = kp;
            float4 vv = *(const float4*)&Vbase[(size_t)(kt + row) * HD + lcol];
            uint4 vp;
            vp.x = cvt_tf32(vv.x); vp.y = cvt_tf32(vv.y);
            vp.z = cvt_tf32(vv.z); vp.w = cvt_tf32(vv.w);
            *(uint4*)&Vs[row * VST + lcol] = vp;
        }
        __syncthreads();

        // ---- S = Q @ K^T : d-frags [q16][key-tile nt] ----
        float sacc[8][4];
        #pragma unroll
        for (int nt = 0; nt < 8; nt++)
            #pragma unroll
            for (int j = 0; j < 4; j++) sacc[nt][j] = 0.0f;

        #pragma unroll
        for (int ks = 0; ks < 8; ks++) {
            #pragma unroll
            for (int nt = 0; nt < 8; nt++) {
                uint32_t bf[2];
                const int base = (nt * 8 + r) * KST + ks * 8 + c;
                bf[0] = Ks[base];
                bf[1] = Ks[base + 4];
                mma_tf32(sacc[nt], qf[ks], bf);
            }
        }

        // ---- Online softmax (keys live in-thread + lanes c: shfl 1,2) ----
        float mx0 = -1e30f, mx1 = -1e30f;
        #pragma unroll
        for (int nt = 0; nt < 8; nt++) {
            mx0 = fmaxf(mx0, fmaxf(sacc[nt][0], sacc[nt][1]));
            mx1 = fmaxf(mx1, fmaxf(sacc[nt][2], sacc[nt][3]));
        }
        mx0 = fmaxf(mx0, __shfl_xor_sync(0xffffffffu, mx0, 1));
        mx0 = fmaxf(mx0, __shfl_xor_sync(0xffffffffu, mx0, 2));
        mx1 = fmaxf(mx1, __shfl_xor_sync(0xffffffffu, mx1, 1));
        mx1 = fmaxf(mx1, __shfl_xor_sync(0xffffffffu, mx1, 2));

        const float mn0 = fmaxf(m0, mx0);
        const float mn1 = fmaxf(m1, mx1);
        const float corr0 = __expf(m0 - mn0);
        const float corr1 = __expf(m1 - mn1);
        m0 = mn0; m1 = mn1;

        float s0 = 0.0f, s1 = 0.0f;
        #pragma unroll
        for (int nt = 0; nt < 8; nt++) {
            sacc[nt][0] = __expf(sacc[nt][0] - m0);
            sacc[nt][1] = __expf(sacc[nt][1] - m0);
            sacc[nt][2] = __expf(sacc[nt][2] - m1);
            sacc[nt][3] = __expf(sacc[nt][3] - m1);
            s0 += sacc[nt][0] + sacc[nt][1];
            s1 += sacc[nt][2] + sacc[nt][3];
        }
        s0 += __shfl_xor_sync(0xffffffffu, s0, 1);
        s0 += __shfl_xor_sync(0xffffffffu, s0, 2);
        s1 += __shfl_xor_sync(0xffffffffu, s1, 1);
        s1 += __shfl_xor_sync(0xffffffffu, s1, 2);
        l0 = l0 * corr0 + s0;
        l1 = l1 * corr1 + s1;

        #pragma unroll
        for (int nt = 0; nt < 8; nt++) {
            oacc[nt][0] *= corr0; oacc[nt][1] *= corr0;
            oacc[nt][2] *= corr1; oacc[nt][3] *= corr1;
        }

        // ---- O += P @ V : P a-frags via shfl from S d-frags ----
        #pragma unroll
        for (int kk = 0; kk < 8; kk++) {
            // a-frag: pa0=P[r][8kk+c], pa1=P[r+8][8kk+c],
            //         pa2=P[r][8kk+c+4], pa3=P[r+8][8kk+c+4]
            const float v00 = __shfl_sync(0xffffffffu, sacc[kk][0], s1l);
            const float v01 = __shfl_sync(0xffffffffu, sacc[kk][1], s1l);
            const float v20 = __shfl_sync(0xffffffffu, sacc[kk][2], s1l);
            const float v21 = __shfl_sync(0xffffffffu, sacc[kk][3], s1l);
            const float w00 = __shfl_sync(0xffffffffu, sacc[kk][0], s2l);
            const float w01 = __shfl_sync(0xffffffffu, sacc[kk][1], s2l);
            const float w20 = __shfl_sync(0xffffffffu, sacc[kk][2], s2l);
            const float w21 = __shfl_sync(0xffffffffu, sacc[kk][3], s2l);
            uint32_t pa[4];
            pa[0] = cvt_tf32(codd ? v01 : v00);
            pa[1] = cvt_tf32(codd ? v21 : v20);
            pa[2] = cvt_tf32(codd ? w01 : w00);
            pa[3] = cvt_tf32(codd ? w21 : w20);

            #pragma unroll
            for (int nt = 0; nt < 8; nt++) {
                uint32_t bf[2];
                bf[0] = Vs[(kk * 8 + c) * VST + nt * 8 + r];
                bf[1] = Vs[(kk * 8 + c + 4) * VST + nt * 8 + r];
                mma_tf32(oacc[nt], pa, bf);
            }
        }
        __syncthreads();   // protect Ks/Vs before next tile's stores
    }

    // ---- Epilogue: normalize, write [B,S,E] ----
    const int b = bh >> 4, h = bh & 15;
    const float inv0 = 1.0f / l0;
    const float inv1 = 1.0f / l1;
    const int qg0 = qb * 64 + w * 16 + r;
    const int qg1 = qg0 + 8;
    #pragma unroll
    for (int nt = 0; nt < 8; nt++) {
        const int col = h * HD + nt * 8 + 2 * c;
        float2 o0, o1;
        o0.x = oacc[nt][0] * inv0; o0.y = oacc[nt][1] * inv0;
        o1.x = oacc[nt][2] * inv1; o1.y = oacc[nt][3] * inv1;
        *(float2*)&g_O[((size_t)(b * SEQ + qg0)) * EMB + col] = o0;
        *(float2*)&g_O[((size_t)(b * SEQ + qg1)) * EMB + col] = o1;
    }
}

// ---------------------------------------------------------------------------
extern "C" void kernel_launch(void* const* d_in, const int* in_sizes, int n_in,
                              void* d_out, int out_size)
{
    const float* x  = (const float*)d_in[0];
    const float* Wq = (const float*)d_in[1];
    const float* bq = (const float*)d_in[2];
    const float* Wk = (const float*)d_in[3];
    const float* bk = (const float*)d_in[4];
    const float* Wv = (const float*)d_in[5];
    const float* bv = (const float*)d_in[6];
    const float* Wo = (const float*)d_in[7];
    const float* bo = (const float*)d_in[8];
    float* out = (float*)d_out;

    // 1) QKV projections (tf32 mma.sync + cp.async pipeline) -> head-major
    qkv_gemm_kernel<<<dim3(EMB / 128, MROWS / 128, 3), 256>>>(
        x, Wq, bq, Wk, bk, Wv, bv);

    // 2) Flash attention (tf32 mma.sync, shfl P-rearrange) -> g_O [B,S,E]
    attn_kernel<<<dim3(SEQ / 64, BATCH * NH), 128>>>();

    // 3) Output projection (tf32 mma.sync + cp.async pipeline) -> d_out
    proj_gemm_kernel<<<dim3(EMB / 128, MROWS / 128), 256>>>(Wo, bo, out);
}